// round 12
// baseline (speedup 1.0000x reference)
#include <cuda_runtime.h>
#include <cstdint>

#define IMG_W 4096
#define IMG_H 4096
#define PX    4   // pixels per thread in x; 2 rows per thread => 8 px/thread

// Load 6 consecutive floats (cols x0-1 .. x0+4) of row yy, zero-padded in y.
__device__ __forceinline__ void load_row6(float* n, const float* __restrict__ img,
                                          int yy, int x0, bool lft, bool rgt) {
    if ((unsigned)yy >= (unsigned)IMG_H) {
#pragma unroll
        for (int i = 0; i < 6; i++) n[i] = 0.0f;
        return;
    }
    const float* p = img + (size_t)yy * IMG_W + x0;
    float4 v = __ldg(reinterpret_cast<const float4*>(p));
    n[1] = v.x; n[2] = v.y; n[3] = v.z; n[4] = v.w;
    n[0] = lft ? __ldg(p - 1) : 0.0f;
    n[5] = rgt ? __ldg(p + PX) : 0.0f;
}

// Codes for 4 pixels. Decision procedure bit-identical to the 37.3us kernel:
// compare tmp +/- di where tmp = float_bits(P) & ~7; exact ties -> first
// index on both sides. Work is split across pipes:
//   ALU: 8 fused mask+attach LOP3, two 4-op VIMNMX3 trees, 2 decode LOP3
//   FMA: 7+1 forced IMADs (opaque multiplier) + FADD sums + bias convert
__device__ __forceinline__ void kirsch_px4(const float n0[6], const float n1[6],
                                           const float n2[6], float code[PX],
                                           int one, int maskReg) {
    float pt[PX + 1], pb[PX + 1], V[PX + 2];
#pragma unroll
    for (int i = 0; i < PX + 1; i++) {
        pt[i] = n0[i] + n0[i + 1];
        pb[i] = n2[i] + n2[i + 1];
    }
#pragma unroll
    for (int i = 0; i < PX + 2; i++) V[i] = n0[i] + n1[i] + n2[i];

#pragma unroll
    for (int j = 1; j <= PX; j++) {
        const float c = n0[j + 1];
        const float d = n1[j - 1];
        const float e = n1[j + 1];
        const float h = n2[j + 1];

        // Kirsch response R_k = 8*P_k - 3*T (T per-pixel const) => order by P_k.
        float P[8];
        P[0] = V[j + 1];        // c+e+h  (N)
        P[1] = pt[j] + e;       // b+c+e  (NW)
        P[2] = pt[j - 1] + c;   // a+b+c  (W)
        P[3] = pt[j - 1] + d;   // a+b+d  (SW)
        P[4] = V[j - 1];        // a+d+f  (S)
        P[5] = pb[j - 1] + d;   // d+f+g  (SE)
        P[6] = pb[j - 1] + h;   // f+g+h  (E)
        P[7] = pb[j] + e;       // e+g+h  (NE)

        // emin[di] = (bits & ~7) | di  -- ONE LOP3 (bits reg, mask reg, di imm).
        // Low bits clear => emin == tmp + di exactly.
        int emin[8];
#pragma unroll
        for (int di = 0; di < 8; di++)
            emin[di] = (((int)__float_as_uint(P[di])) & maskReg) | di;

        // emax[di] = tmp - di = emin[di] - 2*di, forced onto the FMA pipe as
        // IMAD(emin, one, -2di) with 'one' runtime-opaque (== 1).
        int emax1 = emin[1] * one - 2;
        int emax2 = emin[2] * one - 4;
        int emax3 = emin[3] * one - 6;
        int emax4 = emin[4] * one - 8;
        int emax5 = emin[5] * one - 10;
        int emax6 = emin[6] * one - 12;
        int emax7 = emin[7] * one - 14;

        // 3-input min/max trees (depth 2). Ties: min side picks smallest di
        // (+di ascending); max side values tmp-di strictly decrease with di,
        // so equal tmp also picks smallest di. Matches jnp.argmax/argmin.
        int wmin = __vimin3_s32(emin[0], emin[1], emin[2]);
        int tA   = __vimin3_s32(emin[3], emin[4], emin[5]);
        int tB   = min(emin[6], emin[7]);
        wmin = __vimin3_s32(wmin, tA, tB);

        int wmax = __vimax3_s32(emin[0], emax1, emax2);
        int uA   = __vimax3_s32(emax3, emax4, emax5);
        int uB   = max(emax6, emax7);
        wmax = __vimax3_s32(wmax, uA, uB);

        // am = (-wmax)&7 ; ( -8*wmax )&56 == 8*am since tmp_w*8 is mult of 64.
        // IMAD(wmax, -8*one, 0) keeps the multiply on the FMA pipe.
        int t1 = wmax * (-8 * one);
        unsigned cb = ((unsigned)t1 & 56u) | 0x4B000000u | ((unsigned)wmin & 7u);
        code[j - 1] = __uint_as_float(cb) - 8388608.0f;  // exponent-bias I2F
    }
}

// 2 output rows per thread: rows y, y+1 need input rows y-1..y+2 (4 loads).
__global__ __launch_bounds__(256)
void kirsch_mask_kernel(const float* __restrict__ img, float* __restrict__ out) {
    const int x0 = (blockIdx.x * blockDim.x + threadIdx.x) * PX;
    const int y  = blockIdx.y * 2;
    const bool lft = (x0 > 0);
    const bool rgt = (x0 + PX < IMG_W);

    // Runtime-opaque constants (blockDim.x == 256) so ptxas cannot
    // strength-reduce the IMADs back onto the ALU pipe.
    const int one     = (int)(blockDim.x >> 8);            // 1
    const int maskReg = ~((int)(blockDim.x >> 5) - 1);     // ~7 = 0xFFFFFFF8

    float r0[6], r1[6], r2[6], r3[6];
    load_row6(r0, img, y - 1, x0, lft, rgt);
    load_row6(r1, img, y,     x0, lft, rgt);
    load_row6(r2, img, y + 1, x0, lft, rgt);
    load_row6(r3, img, y + 2, x0, lft, rgt);

    float code[PX];
    kirsch_px4(r0, r1, r2, code, one, maskReg);
    float4* oA = reinterpret_cast<float4*>(out + (size_t)y * IMG_W + x0);
    *oA = make_float4(code[0], code[1], code[2], code[3]);

    kirsch_px4(r1, r2, r3, code, one, maskReg);
    float4* oB = reinterpret_cast<float4*>(out + (size_t)(y + 1) * IMG_W + x0);
    *oB = make_float4(code[0], code[1], code[2], code[3]);
}

extern "C" void kernel_launch(void* const* d_in, const int* in_sizes, int n_in,
                              void* d_out, int out_size) {
    const float* img = (const float*)d_in[0];
    for (int i = 0; i < n_in; i++) {
        if (in_sizes[i] == IMG_W * IMG_H) { img = (const float*)d_in[i]; break; }
    }
    float* out = (float*)d_out;

    dim3 block(256, 1, 1);
    dim3 grid(IMG_W / (256 * PX), IMG_H / 2, 1);  // (4, 2048)
    kirsch_mask_kernel<<<grid, block>>>(img, out);
}

// round 13
// speedup vs baseline: 1.0206x; 1.0206x over previous
#include <cuda_runtime.h>
#include <cstdint>

#define IMG_W 4096
#define IMG_H 4096
#define PX    4   // pixels per thread in x; 2 rows per thread => 8 px/thread

// Load 6 consecutive floats (cols x0-1 .. x0+4) of row yy, zero-padded in y.
__device__ __forceinline__ void load_row6(float* n, const float* __restrict__ img,
                                          int yy, int x0, bool lft, bool rgt) {
    if ((unsigned)yy >= (unsigned)IMG_H) {
#pragma unroll
        for (int i = 0; i < 6; i++) n[i] = 0.0f;
        return;
    }
    const float* p = img + (size_t)yy * IMG_W + x0;
    float4 v = __ldg(reinterpret_cast<const float4*>(p));
    n[1] = v.x; n[2] = v.y; n[3] = v.z; n[4] = v.w;
    n[0] = lft ? __ldg(p - 1) : 0.0f;
    n[5] = rgt ? __ldg(p + PX) : 0.0f;
}

// Codes for 4 pixels. Decision procedure bit-identical to the 37.3us kernel:
// compare tmp +/- di where tmp = float_bits(P) & ~7; exact ties -> first
// index on both sides. Work split across pipes:
//   ALU: 8 fused mask+attach LOP3, two 4-op VIMNMX3 trees, 2 decode LOP3
//   FMA: 7+1 forced IMADs (opaque multiplier) + FADD sums + bias convert
__device__ __forceinline__ void kirsch_px4(const float n0[6], const float n1[6],
                                           const float n2[6], float code[PX],
                                           int one, int maskReg) {
    float pt[PX + 1], pb[PX + 1], V[PX + 2];
#pragma unroll
    for (int i = 0; i < PX + 1; i++) {
        pt[i] = n0[i] + n0[i + 1];
        pb[i] = n2[i] + n2[i + 1];
    }
#pragma unroll
    for (int i = 0; i < PX + 2; i++) V[i] = n0[i] + n1[i] + n2[i];

#pragma unroll
    for (int j = 1; j <= PX; j++) {
        const float c = n0[j + 1];
        const float d = n1[j - 1];
        const float e = n1[j + 1];
        const float h = n2[j + 1];

        // Kirsch response R_k = 8*P_k - 3*T (T per-pixel const) => order by P_k.
        float P[8];
        P[0] = V[j + 1];        // c+e+h  (N)
        P[1] = pt[j] + e;       // b+c+e  (NW)
        P[2] = pt[j - 1] + c;   // a+b+c  (W)
        P[3] = pt[j - 1] + d;   // a+b+d  (SW)
        P[4] = V[j - 1];        // a+d+f  (S)
        P[5] = pb[j - 1] + d;   // d+f+g  (SE)
        P[6] = pb[j - 1] + h;   // f+g+h  (E)
        P[7] = pb[j] + e;       // e+g+h  (NE)

        // emin[di] = (bits & ~7) | di  -- ONE LOP3 (bits reg, mask reg, di imm).
        // Low bits clear => emin == tmp + di exactly.
        int emin[8];
#pragma unroll
        for (int di = 0; di < 8; di++)
            emin[di] = (((int)__float_as_uint(P[di])) & maskReg) | di;

        // emax[di] = tmp - di = emin[di] - 2*di, forced onto the FMA pipe as
        // IMAD(emin, one, -2di) with 'one' runtime-opaque (== 1).
        // Consume each emax immediately in the tree to keep live ranges short.
        int wmax = __vimax3_s32(emin[0], emin[1] * one - 2, emin[2] * one - 4);
        int uA   = __vimax3_s32(emin[3] * one - 6, emin[4] * one - 8,
                                emin[5] * one - 10);
        int uB   = max(emin[6] * one - 12, emin[7] * one - 14);
        wmax = __vimax3_s32(wmax, uA, uB);

        // min tree: ties pick smallest di (+di ascending). Max side values
        // tmp-di strictly decrease with di, so equal tmp also picks smallest
        // di. Matches jnp.argmax/argmin first-index semantics.
        int wmin = __vimin3_s32(emin[0], emin[1], emin[2]);
        int tA   = __vimin3_s32(emin[3], emin[4], emin[5]);
        int tB   = min(emin[6], emin[7]);
        wmin = __vimin3_s32(wmin, tA, tB);

        // am = (-wmax)&7 ; (-8*wmax)&56 == 8*am since tmp_w*8 is mult of 64.
        // IMAD(wmax, -8*one, 0) keeps the multiply on the FMA pipe.
        int t1 = wmax * (-8 * one);
        unsigned cb = ((unsigned)t1 & 56u) | 0x4B000000u | ((unsigned)wmin & 7u);
        code[j - 1] = __uint_as_float(cb) - 8388608.0f;  // exponent-bias I2F
    }
}

// 2 output rows per thread: rows y, y+1 need input rows y-1..y+2 (4 loads).
// minBlocks=6 caps regs at 42 (R12's natural 48 -> occ 52%; a 6-reg trim
// recovers 6 CTAs/SM without R11's rematerialization blowup at 32).
__global__ __launch_bounds__(256, 6)
void kirsch_mask_kernel(const float* __restrict__ img, float* __restrict__ out) {
    const int x0 = (blockIdx.x * blockDim.x + threadIdx.x) * PX;
    const int y  = blockIdx.y * 2;
    const bool lft = (x0 > 0);
    const bool rgt = (x0 + PX < IMG_W);

    // Runtime-opaque constants (blockDim.x == 256) so ptxas cannot
    // strength-reduce the IMADs back onto the ALU pipe.
    const int one     = (int)(blockDim.x >> 8);            // 1
    const int maskReg = ~((int)(blockDim.x >> 5) - 1);     // ~7 = 0xFFFFFFF8

    float r0[6], r1[6], r2[6], r3[6];
    load_row6(r0, img, y - 1, x0, lft, rgt);
    load_row6(r1, img, y,     x0, lft, rgt);
    load_row6(r2, img, y + 1, x0, lft, rgt);
    load_row6(r3, img, y + 2, x0, lft, rgt);

    float code[PX];
    kirsch_px4(r0, r1, r2, code, one, maskReg);
    float4* oA = reinterpret_cast<float4*>(out + (size_t)y * IMG_W + x0);
    *oA = make_float4(code[0], code[1], code[2], code[3]);

    kirsch_px4(r1, r2, r3, code, one, maskReg);
    float4* oB = reinterpret_cast<float4*>(out + (size_t)(y + 1) * IMG_W + x0);
    *oB = make_float4(code[0], code[1], code[2], code[3]);
}

extern "C" void kernel_launch(void* const* d_in, const int* in_sizes, int n_in,
                              void* d_out, int out_size) {
    const float* img = (const float*)d_in[0];
    for (int i = 0; i < n_in; i++) {
        if (in_sizes[i] == IMG_W * IMG_H) { img = (const float*)d_in[i]; break; }
    }
    float* out = (float*)d_out;

    dim3 block(256, 1, 1);
    dim3 grid(IMG_W / (256 * PX), IMG_H / 2, 1);  // (4, 2048)
    kirsch_mask_kernel<<<grid, block>>>(img, out);
}